// round 1
// baseline (speedup 1.0000x reference)
#include <cuda_runtime.h>

// Problem constants (fixed shapes per reference)
#define NTOK  (32 * 8192)   // 262144 tokens
#define DIM   256           // input dim (K)
#define NEXP  16            // experts
#define POUT  64            // output dim (N)

#define BM    128           // tokens per tile
#define BK    32            // K chunk
#define TM    8             // tokens per thread
#define TN    4             // cols per thread
// block: 256 threads = 16 (cols) x 16 (rows)

// ---------------- scratch (no allocations allowed) ----------------
__device__ int g_sorted[NTOK];
__device__ int g_counts[NEXP];
__device__ int g_offsets[NEXP + 1];
__device__ int g_cursor[NEXP];

// ---------------- routing kernels ----------------
__global__ void k_init() {
    int t = threadIdx.x;
    if (t < NEXP) g_counts[t] = 0;
}

__global__ void k_hist(const int* __restrict__ idx) {
    __shared__ int sc[NEXP];
    int t = threadIdx.x;
    if (t < NEXP) sc[t] = 0;
    __syncthreads();
    int i = blockIdx.x * blockDim.x + t;
    int stride = gridDim.x * blockDim.x;
    for (; i < NTOK; i += stride) atomicAdd(&sc[idx[i]], 1);
    __syncthreads();
    if (t < NEXP && sc[t] > 0) atomicAdd(&g_counts[t], sc[t]);
}

__global__ void k_scan() {
    if (threadIdx.x == 0) {
        int acc = 0;
        for (int e = 0; e < NEXP; e++) {
            g_offsets[e] = acc;
            g_cursor[e]  = acc;
            acc += g_counts[e];
        }
        g_offsets[NEXP] = acc;
    }
}

__global__ void k_scatter(const int* __restrict__ idx) {
    __shared__ int sc[NEXP];
    __shared__ int sbase[NEXP];
    int t = threadIdx.x;
    if (t < NEXP) sc[t] = 0;
    __syncthreads();
    int i = blockIdx.x * blockDim.x + t;
    int e = 0, local = 0;
    bool valid = (i < NTOK);
    if (valid) {
        e = idx[i];
        local = atomicAdd(&sc[e], 1);
    }
    __syncthreads();
    if (t < NEXP && sc[t] > 0) sbase[t] = atomicAdd(&g_cursor[t], sc[t]);
    __syncthreads();
    if (valid) g_sorted[sbase[e] + local] = i;
}

// ---------------- grouped GEMM ----------------
// out[row] = x[row] @ W[e] + b[e] for rows grouped by expert e.
__global__ void __launch_bounds__(256)
k_gemm(const float* __restrict__ x, const float* __restrict__ W,
       const float* __restrict__ bias, float* __restrict__ out) {
    // Locate (expert, tile) for this flat block index.
    int tile = blockIdx.x;
    int e = -1, m0 = 0;
    int accT = 0;
#pragma unroll
    for (int i = 0; i < NEXP; i++) {
        int cnt_i = g_offsets[i + 1] - g_offsets[i];
        int nt = (cnt_i + BM - 1) / BM;
        if (e < 0 && tile < accT + nt) {
            e = i;
            m0 = (tile - accT) * BM;
        }
        accT += nt;
    }
    if (e < 0) return;  // past the last real tile

    int start = g_offsets[e];
    int cnt   = g_offsets[e + 1] - start;

    __shared__ float Xs[BK][BM + 1];  // transposed x tile, +1 pad -> conflict-free
    __shared__ float Ws[BK][POUT];
    __shared__ int   rows[BM];

    int tid = threadIdx.x;
    int tx = tid & 15;  // col group: cols tx*4 .. tx*4+3
    int ty = tid >> 4;  // row group: tokens ty*8 .. ty*8+7

    if (tid < BM) {
        int m = m0 + tid;
        rows[tid] = (m < cnt) ? g_sorted[start + m] : -1;
    }
    __syncthreads();

    // packed f32x2 accumulators (bit pattern 0 == {0.0f, 0.0f})
    unsigned long long acc01[TM], acc23[TM];
#pragma unroll
    for (int i = 0; i < TM; i++) { acc01[i] = 0ull; acc23[i] = 0ull; }

    const float* Wbase = W + (size_t)e * DIM * POUT;

    for (int k0 = 0; k0 < DIM; k0 += BK) {
        // Load X tile (gathered rows), store transposed into Xs[k][m].
#pragma unroll
        for (int i = 0; i < 4; i++) {
            int v = tid + i * 256;     // 0..1023 float4s
            int m = v >> 3;            // token within tile
            int kq = v & 7;            // float4 within 32-float K chunk
            int row = rows[m];
            float4 f = make_float4(0.f, 0.f, 0.f, 0.f);
            if (row >= 0)
                f = *reinterpret_cast<const float4*>(x + (size_t)row * DIM + k0 + kq * 4);
            Xs[kq * 4 + 0][m] = f.x;
            Xs[kq * 4 + 1][m] = f.y;
            Xs[kq * 4 + 2][m] = f.z;
            Xs[kq * 4 + 3][m] = f.w;
        }
        // Load W chunk: Ws[k][p]
#pragma unroll
        for (int i = 0; i < 2; i++) {
            int v = tid + i * 256;     // 0..511 float4s
            int k = v >> 4;
            int p = (v & 15) * 4;
            *reinterpret_cast<float4*>(&Ws[k][p]) =
                *reinterpret_cast<const float4*>(Wbase + (size_t)(k0 + k) * POUT + p);
        }
        __syncthreads();

#pragma unroll
        for (int kk = 0; kk < BK; kk++) {
            float4 wv = *reinterpret_cast<float4*>(&Ws[kk][tx * TN]);
            unsigned long long wb01, wb23;
            asm("mov.b64 %0, {%1,%2};" : "=l"(wb01) : "f"(wv.x), "f"(wv.y));
            asm("mov.b64 %0, {%1,%2};" : "=l"(wb23) : "f"(wv.z), "f"(wv.w));
#pragma unroll
            for (int i = 0; i < TM; i++) {
                float xm = Xs[kk][ty * TM + i];
                unsigned long long xb;
                asm("mov.b64 %0, {%1,%1};" : "=l"(xb) : "f"(xm));
                asm("fma.rn.f32x2 %0, %1, %2, %0;" : "+l"(acc01[i]) : "l"(xb), "l"(wb01));
                asm("fma.rn.f32x2 %0, %1, %2, %0;" : "+l"(acc23[i]) : "l"(xb), "l"(wb23));
            }
        }
        __syncthreads();
    }

    // Epilogue: add bias, scatter rows to output.
    float4 bv = *reinterpret_cast<const float4*>(bias + e * POUT + tx * TN);
#pragma unroll
    for (int i = 0; i < TM; i++) {
        int row = rows[ty * TM + i];
        if (row >= 0) {
            float a0, a1, a2, a3;
            asm("mov.b64 {%0,%1}, %2;" : "=f"(a0), "=f"(a1) : "l"(acc01[i]));
            asm("mov.b64 {%0,%1}, %2;" : "=f"(a2), "=f"(a3) : "l"(acc23[i]));
            float4 o = make_float4(a0 + bv.x, a1 + bv.y, a2 + bv.z, a3 + bv.w);
            *reinterpret_cast<float4*>(out + (size_t)row * POUT + tx * TN) = o;
        }
    }
}

// ---------------- launch ----------------
extern "C" void kernel_launch(void* const* d_in, const int* in_sizes, int n_in,
                              void* d_out, int out_size) {
    const float* x   = (const float*)d_in[0];  // [32,8192,256]
    const float* W   = (const float*)d_in[1];  // [16,256,64]
    const float* b   = (const float*)d_in[2];  // [16,64]
    const int*   idx = (const int*)d_in[3];    // [32,8192]
    float* out = (float*)d_out;                // [32,8192,64]

    k_init<<<1, 32>>>();
    k_hist<<<512, 256>>>(idx);
    k_scan<<<1, 32>>>();
    k_scatter<<<NTOK / 256, 256>>>(idx);

    int max_tiles = NTOK / BM + NEXP;  // upper bound on sum of per-expert tiles
    k_gemm<<<max_tiles, 256>>>(x, W, b, out);
}

// round 4
// speedup vs baseline: 1.5741x; 1.5741x over previous
#include <cuda_runtime.h>
#include <cuda_bf16.h>
#include <cstdint>

// Problem constants (fixed shapes per reference)
#define NTOK  (32 * 8192)   // 262144 tokens
#define DIM   256           // K
#define NEXP  16
#define POUT  64            // N
#define BM    128           // tokens per tile
#define CK    64            // K per chunk
#define NCH   (DIM / CK)    // 4 chunks

// ---------------- scratch ----------------
__device__ int g_sorted[NTOK];
__device__ int g_counts[NEXP];
__device__ int g_offsets[NEXP + 1];
__device__ int g_cursor[NEXP];

// ---------------- routing ----------------
__global__ void k_init() {
    int t = threadIdx.x;
    if (t < NEXP) g_counts[t] = 0;
}

__global__ void k_hist(const int* __restrict__ idx) {
    __shared__ int sc[NEXP];
    int t = threadIdx.x;
    if (t < NEXP) sc[t] = 0;
    __syncthreads();
    int i = blockIdx.x * blockDim.x + t;   // one int4 per thread, grid covers all
    int4 v = reinterpret_cast<const int4*>(idx)[i];
    atomicAdd(&sc[v.x], 1);
    atomicAdd(&sc[v.y], 1);
    atomicAdd(&sc[v.z], 1);
    atomicAdd(&sc[v.w], 1);
    __syncthreads();
    if (t < NEXP && sc[t] > 0) atomicAdd(&g_counts[t], sc[t]);
}

__global__ void k_scan() {
    if (threadIdx.x == 0) {
        int acc = 0;
        for (int e = 0; e < NEXP; e++) {
            g_offsets[e] = acc;
            g_cursor[e]  = acc;
            acc += g_counts[e];
        }
        g_offsets[NEXP] = acc;
    }
}

__global__ void k_scatter(const int* __restrict__ idx) {
    __shared__ int sc[NEXP];
    __shared__ int sbase[NEXP];
    int t = threadIdx.x;
    if (t < NEXP) sc[t] = 0;
    __syncthreads();
    int i = blockIdx.x * blockDim.x + t;
    int e = idx[i];
    int local = atomicAdd(&sc[e], 1);
    __syncthreads();
    if (t < NEXP && sc[t] > 0) sbase[t] = atomicAdd(&g_cursor[t], sc[t]);
    __syncthreads();
    g_sorted[sbase[e] + local] = i;
}

// ---------------- helpers ----------------
__device__ __forceinline__ uint32_t s2u(const void* p) {
    uint32_t a;
    asm("{ .reg .u64 t; cvta.to.shared.u64 t, %1; cvt.u32.u64 %0, t; }" : "=r"(a) : "l"(p));
    return a;
}
__device__ __forceinline__ uint32_t sw128(uint32_t o) { return o ^ ((o >> 3) & 0x70); }

__device__ __forceinline__ void ldsm_x4(uint32_t addr, uint32_t r[4]) {
    asm volatile("ldmatrix.sync.aligned.m8n8.x4.shared.b16 {%0,%1,%2,%3}, [%4];"
                 : "=r"(r[0]), "=r"(r[1]), "=r"(r[2]), "=r"(r[3]) : "r"(addr));
}
__device__ __forceinline__ void ldsm_x4_t(uint32_t addr, uint32_t r[4]) {
    asm volatile("ldmatrix.sync.aligned.m8n8.x4.trans.shared.b16 {%0,%1,%2,%3}, [%4];"
                 : "=r"(r[0]), "=r"(r[1]), "=r"(r[2]), "=r"(r[3]) : "r"(addr));
}
__device__ __forceinline__ void mma16816(float c[4], const uint32_t a[4],
                                         uint32_t b0, uint32_t b1) {
    asm volatile(
        "mma.sync.aligned.m16n8k16.row.col.f32.bf16.bf16.f32 "
        "{%0,%1,%2,%3}, {%4,%5,%6,%7}, {%8,%9}, {%0,%1,%2,%3};"
        : "+f"(c[0]), "+f"(c[1]), "+f"(c[2]), "+f"(c[3])
        : "r"(a[0]), "r"(a[1]), "r"(a[2]), "r"(a[3]), "r"(b0), "r"(b1));
}

// split fp32 float4 -> packed bf16 hi (truncated, exact bits) + bf16 lo (residual)
__device__ __forceinline__ void split4(float4 f, uint2& hv, uint2& lv) {
    uint32_t bx = __float_as_uint(f.x), by = __float_as_uint(f.y);
    uint32_t bz = __float_as_uint(f.z), bw = __float_as_uint(f.w);
    hv.x = __byte_perm(bx, by, 0x7632);
    hv.y = __byte_perm(bz, bw, 0x7632);
    float lx = f.x - __uint_as_float(bx & 0xFFFF0000u);
    float ly = f.y - __uint_as_float(by & 0xFFFF0000u);
    float lz = f.z - __uint_as_float(bz & 0xFFFF0000u);
    float lw = f.w - __uint_as_float(bw & 0xFFFF0000u);
    asm("cvt.rn.bf16x2.f32 %0, %1, %2;" : "=r"(lv.x) : "f"(ly), "f"(lx));
    asm("cvt.rn.bf16x2.f32 %0, %1, %2;" : "=r"(lv.y) : "f"(lw), "f"(lz));
}

// ---------------- smem layout ----------------
// [0:256)    bias (64 f32)
// [256:768)  rows (128 int)
// [1024:)    A_hi 16K | A_lo 16K | B_hi 8K | B_lo 8K  (48 KB)
// epilogue: C tile (128 x 68 f32 = 34 KB) overlays the 48 KB buffer
#define SM_BIAS 0
#define SM_ROWS 256
#define SM_BUF  1024
#define SMEM_TOTAL (SM_BUF + 49152)
#define CS_STRIDE 68

// ---------------- grouped GEMM via mma.sync bf16 split ----------------
__global__ void __launch_bounds__(256, 2)
k_gemm_mma(const float* __restrict__ x, const float* __restrict__ W,
           const float* __restrict__ bias, float* __restrict__ out) {
    // tile -> (expert, m0)
    int tile = blockIdx.x;
    int e = -1, m0 = 0, accT = 0;
#pragma unroll
    for (int i = 0; i < NEXP; i++) {
        int cnt_i = g_offsets[i + 1] - g_offsets[i];
        int nt = (cnt_i + BM - 1) / BM;
        if (e < 0 && tile < accT + nt) { e = i; m0 = (tile - accT) * BM; }
        accT += nt;
    }
    if (e < 0) return;
    int start = g_offsets[e];
    int cnt   = g_offsets[e + 1] - start;

    extern __shared__ char smem[];
    uint32_t sb = s2u(smem);
    float* bias_s = (float*)(smem + SM_BIAS);
    int*   rows   = (int*)(smem + SM_ROWS);

    const uint32_t AHI = sb + SM_BUF;
    const uint32_t ALO = AHI + 16384;
    const uint32_t BHI = AHI + 32768;
    const uint32_t BLO = AHI + 40960;

    int tid = threadIdx.x;
    int wid = tid >> 5, L = tid & 31;

    if (tid < BM) {
        int m = m0 + tid;
        rows[tid] = (m < cnt) ? g_sorted[start + m] : -1;
    }
    if (tid < 16)
        *(float4*)(bias_s + tid * 4) = *(const float4*)(bias + e * POUT + tid * 4);
    __syncthreads();

    // ldmatrix lane-address components (bytes, pre-swizzle)
    int arow = wid * 16 + (L & 7) + ((L >> 3) & 1) * 8;   // A row for this lane
    int acol = (L >> 4) * 8;                              // A col (bf16 elems)
    int brow = (L & 7) + ((L >> 3) & 1) * 8;              // B k-row base
    int bcol = (L >> 4) * 8;                              // B n base

    float acc[8][4];
#pragma unroll
    for (int j = 0; j < 8; j++)
#pragma unroll
        for (int q = 0; q < 4; q++) acc[j][q] = 0.f;

    const float* Wbase = W + (size_t)e * DIM * POUT;

    for (int c = 0; c < NCH; c++) {
        int k0 = c * CK;
        // Prefetch A (gathered) into registers: overlaps previous chunk's MMAs.
        float4 fa[8];
#pragma unroll
        for (int i = 0; i < 8; i++) {
            int v = tid + i * 256;
            int m = v >> 4, q = v & 15;
            int row = rows[m];
            fa[i] = make_float4(0.f, 0.f, 0.f, 0.f);
            if (row >= 0) fa[i] = *(const float4*)(x + (size_t)row * DIM + k0 + q * 4);
        }
        __syncthreads();   // all warps done with previous chunk's smem
        // A: split + swizzled store (rows of 64 bf16 = 128 B)
#pragma unroll
        for (int i = 0; i < 8; i++) {
            int v = tid + i * 256;
            int m = v >> 4, q = v & 15;
            uint2 hv, lv;
            split4(fa[i], hv, lv);
            uint32_t off = sw128((uint32_t)(m * 128 + q * 8));
            *(uint2*)(smem + SM_BUF + off) = hv;
            *(uint2*)(smem + SM_BUF + 16384 + off) = lv;
        }
        // B: W chunk [64 k x 64 n]
#pragma unroll
        for (int i = 0; i < 4; i++) {
            int v = tid + i * 256;
            int kr = v >> 4, nq = v & 15;
            float4 f = *(const float4*)(Wbase + (size_t)(k0 + kr) * POUT + nq * 4);
            uint2 hv, lv;
            split4(f, hv, lv);
            uint32_t off = sw128((uint32_t)(kr * 128 + nq * 8));
            *(uint2*)(smem + SM_BUF + 32768 + off) = hv;
            *(uint2*)(smem + SM_BUF + 40960 + off) = lv;
        }
        __syncthreads();

#pragma unroll
        for (int s = 0; s < 4; s++) {
            uint32_t aoff = sw128((uint32_t)(arow * 128 + (s * 16 + acol) * 2));
            uint32_t ah[4], al[4];
            ldsm_x4(AHI + aoff, ah);
            ldsm_x4(ALO + aoff, al);
#pragma unroll
            for (int p = 0; p < 4; p++) {
                uint32_t boff = sw128((uint32_t)((s * 16 + brow) * 128 + (p * 16 + bcol) * 2));
                uint32_t bh[4], bl[4];
                ldsm_x4_t(BHI + boff, bh);
                ldsm_x4_t(BLO + boff, bl);
                mma16816(acc[2 * p],     ah, bh[0], bh[1]);
                mma16816(acc[2 * p],     al, bh[0], bh[1]);
                mma16816(acc[2 * p],     ah, bl[0], bl[1]);
                mma16816(acc[2 * p + 1], ah, bh[2], bh[3]);
                mma16816(acc[2 * p + 1], al, bh[2], bh[3]);
                mma16816(acc[2 * p + 1], ah, bl[2], bl[3]);
            }
        }
    }

    // ---- epilogue: transpose through smem, coalesced scatter ----
    __syncthreads();
    float* Cs = (float*)(smem + SM_BUF);
    {
        int r = wid * 16 + (L >> 2);
        int cbase = (L & 3) * 2;
#pragma unroll
        for (int j = 0; j < 8; j++) {
            int cc = cbase + j * 8;
            *(float2*)(Cs + r * CS_STRIDE + cc)       = make_float2(acc[j][0], acc[j][1]);
            *(float2*)(Cs + (r + 8) * CS_STRIDE + cc) = make_float2(acc[j][2], acc[j][3]);
        }
    }
    __syncthreads();
    {
        int r = tid >> 1;
        int half = tid & 1;
        int row = rows[r];
        if (row >= 0) {
            float* op = out + (size_t)row * POUT;
#pragma unroll
            for (int q = 0; q < 8; q++) {
                int c4 = half * 8 + q;
                float4 v = *(float4*)(Cs + r * CS_STRIDE + c4 * 4);
                float4 bv = *(float4*)(bias_s + c4 * 4);
                v.x += bv.x; v.y += bv.y; v.z += bv.z; v.w += bv.w;
                *(float4*)(op + c4 * 4) = v;
            }
        }
    }
}

// ---------------- launch ----------------
extern "C" void kernel_launch(void* const* d_in, const int* in_sizes, int n_in,
                              void* d_out, int out_size) {
    const float* x   = (const float*)d_in[0];  // [32,8192,256]
    const float* W   = (const float*)d_in[1];  // [16,256,64]
    const float* b   = (const float*)d_in[2];  // [16,64]
    const int*   idx = (const int*)d_in[3];    // [32,8192]
    float* out = (float*)d_out;                // [32,8192,64]

    cudaFuncSetAttribute(k_gemm_mma, cudaFuncAttributeMaxDynamicSharedMemorySize, SMEM_TOTAL);

    k_init<<<1, 32>>>();
    k_hist<<<NTOK / (256 * 4), 256>>>(idx);
    k_scan<<<1, 32>>>();
    k_scatter<<<NTOK / 256, 256>>>(idx);

    int max_tiles = NTOK / BM + NEXP;
    k_gemm_mma<<<max_tiles, 256, SMEM_TOTAL>>>(x, W, b, out);
}

// round 5
// speedup vs baseline: 1.7916x; 1.1382x over previous
#include <cuda_runtime.h>
#include <cuda_bf16.h>
#include <cstdint>

// Problem constants (fixed shapes per reference)
#define NTOK  (32 * 8192)   // 262144 tokens
#define DIM   256           // K
#define NEXP  16
#define POUT  64            // N
#define BM    128           // tokens per tile
#define CK    64            // K per chunk
#define NCH   (DIM / CK)    // 4 chunks

// ---------------- scratch ----------------
__device__ int g_sorted[NTOK];
__device__ int g_counts[NEXP];
__device__ int g_offsets[NEXP + 1];
__device__ int g_cursor[NEXP];
// Pre-split W tiles, bf16 hi/lo, stored in swizzled tile byte order.
__device__ unsigned char g_Whi[NEXP][NCH][8192];
__device__ unsigned char g_Wlo[NEXP][NCH][8192];

// ---------------- routing ----------------
__global__ void k_init() {
    int t = threadIdx.x;
    if (t < NEXP) g_counts[t] = 0;
}

__global__ void k_hist(const int* __restrict__ idx) {
    __shared__ int sc[NEXP];
    int t = threadIdx.x;
    if (t < NEXP) sc[t] = 0;
    __syncthreads();
    int i = blockIdx.x * blockDim.x + t;
    int4 v = reinterpret_cast<const int4*>(idx)[i];
    atomicAdd(&sc[v.x], 1);
    atomicAdd(&sc[v.y], 1);
    atomicAdd(&sc[v.z], 1);
    atomicAdd(&sc[v.w], 1);
    __syncthreads();
    if (t < NEXP && sc[t] > 0) atomicAdd(&g_counts[t], sc[t]);
}

__global__ void k_scan() {
    if (threadIdx.x == 0) {
        int acc = 0;
        for (int e = 0; e < NEXP; e++) {
            g_offsets[e] = acc;
            g_cursor[e]  = acc;
            acc += g_counts[e];
        }
        g_offsets[NEXP] = acc;
    }
}

__global__ void k_scatter(const int* __restrict__ idx) {
    __shared__ int sc[NEXP];
    __shared__ int sbase[NEXP];
    int t = threadIdx.x;
    int lane = t & 31;
    if (t < NEXP) sc[t] = 0;
    __syncthreads();
    int i = blockIdx.x * blockDim.x + t;
    int e = idx[i];
    // warp-aggregated shared atomic
    unsigned mask = __match_any_sync(0xffffffffu, e);
    int leader = __ffs(mask) - 1;
    int base = 0;
    if (lane == leader) base = atomicAdd(&sc[e], __popc(mask));
    base = __shfl_sync(0xffffffffu, base, leader);
    int local = base + __popc(mask & ((1u << lane) - 1u));
    __syncthreads();
    if (t < NEXP && sc[t] > 0) sbase[t] = atomicAdd(&g_cursor[t], sc[t]);
    __syncthreads();
    g_sorted[sbase[e] + local] = i;
}

// ---------------- helpers ----------------
__device__ __forceinline__ uint32_t s2u(const void* p) {
    uint32_t a;
    asm("{ .reg .u64 t; cvta.to.shared.u64 t, %1; cvt.u32.u64 %0, t; }" : "=r"(a) : "l"(p));
    return a;
}
__device__ __forceinline__ uint32_t sw128(uint32_t o) { return o ^ ((o >> 3) & 0x70); }

__device__ __forceinline__ void ldsm_x4(uint32_t addr, uint32_t r[4]) {
    asm volatile("ldmatrix.sync.aligned.m8n8.x4.shared.b16 {%0,%1,%2,%3}, [%4];"
                 : "=r"(r[0]), "=r"(r[1]), "=r"(r[2]), "=r"(r[3]) : "r"(addr));
}
__device__ __forceinline__ void ldsm_x4_t(uint32_t addr, uint32_t r[4]) {
    asm volatile("ldmatrix.sync.aligned.m8n8.x4.trans.shared.b16 {%0,%1,%2,%3}, [%4];"
                 : "=r"(r[0]), "=r"(r[1]), "=r"(r[2]), "=r"(r[3]) : "r"(addr));
}
__device__ __forceinline__ void mma16816(float c[4], const uint32_t a[4],
                                         uint32_t b0, uint32_t b1) {
    asm volatile(
        "mma.sync.aligned.m16n8k16.row.col.f32.bf16.bf16.f32 "
        "{%0,%1,%2,%3}, {%4,%5,%6,%7}, {%8,%9}, {%0,%1,%2,%3};"
        : "+f"(c[0]), "+f"(c[1]), "+f"(c[2]), "+f"(c[3])
        : "r"(a[0]), "r"(a[1]), "r"(a[2]), "r"(a[3]), "r"(b0), "r"(b1));
}
__device__ __forceinline__ void cpasync16(uint32_t dst, const void* src) {
    asm volatile("cp.async.cg.shared.global [%0], [%1], 16;"
                 :: "r"(dst), "l"(src) : "memory");
}

// split fp32 float4 -> packed bf16 hi (truncated, exact bits) + bf16 lo (residual)
__device__ __forceinline__ void split4(float4 f, uint2& hv, uint2& lv) {
    uint32_t bx = __float_as_uint(f.x), by = __float_as_uint(f.y);
    uint32_t bz = __float_as_uint(f.z), bw = __float_as_uint(f.w);
    hv.x = __byte_perm(bx, by, 0x7632);
    hv.y = __byte_perm(bz, bw, 0x7632);
    float lx = f.x - __uint_as_float(bx & 0xFFFF0000u);
    float ly = f.y - __uint_as_float(by & 0xFFFF0000u);
    float lz = f.z - __uint_as_float(bz & 0xFFFF0000u);
    float lw = f.w - __uint_as_float(bw & 0xFFFF0000u);
    asm("cvt.rn.bf16x2.f32 %0, %1, %2;" : "=r"(lv.x) : "f"(ly), "f"(lx));
    asm("cvt.rn.bf16x2.f32 %0, %1, %2;" : "=r"(lv.y) : "f"(lw), "f"(lz));
}

// ---------------- W pre-split (once) ----------------
__global__ void k_wsplit(const float* __restrict__ W) {
    int e = blockIdx.x >> 2;
    int c = blockIdx.x & 3;
    int tid = threadIdx.x;
    const float* Wc = W + ((size_t)e * DIM + c * CK) * POUT;
#pragma unroll
    for (int i = 0; i < 4; i++) {
        int v = tid + i * 256;          // 0..1023 float4s
        int kr = v >> 4, nq = v & 15;
        float4 f = *(const float4*)(Wc + (size_t)kr * POUT + nq * 4);
        uint2 hv, lv;
        split4(f, hv, lv);
        uint32_t off = sw128((uint32_t)(kr * 128 + nq * 8));
        *(uint2*)(g_Whi[e][c] + off) = hv;
        *(uint2*)(g_Wlo[e][c] + off) = lv;
    }
}

// ---------------- smem layout ----------------
// [0:256)    bias (64 f32)
// [256:768)  rows (128 int)
// [1024:)    2 x { A_hi 16K | A_lo 16K | B_hi 8K | B_lo 8K }  (2 x 48 KB)
// epilogue:  C tile (128 x 68 f32 = 34.8 KB) overlays buffer 0
#define SM_BIAS 0
#define SM_ROWS 256
#define SM_BUF  1024
#define STAGE   49152
#define SMEM_TOTAL (SM_BUF + 2 * STAGE)   // 99328
#define CS_STRIDE 68

// ---------------- grouped GEMM via mma.sync bf16 split ----------------
__global__ void __launch_bounds__(256, 2)
k_gemm_mma(const float* __restrict__ x, const float* __restrict__ bias,
           float* __restrict__ out) {
    // tile -> (expert, m0)
    int tile = blockIdx.x;
    int e = -1, m0 = 0, accT = 0;
#pragma unroll
    for (int i = 0; i < NEXP; i++) {
        int cnt_i = g_offsets[i + 1] - g_offsets[i];
        int nt = (cnt_i + BM - 1) / BM;
        if (e < 0 && tile < accT + nt) { e = i; m0 = (tile - accT) * BM; }
        accT += nt;
    }
    if (e < 0) return;
    int start = g_offsets[e];
    int cnt   = g_offsets[e + 1] - start;

    extern __shared__ char smem[];
    uint32_t sb = s2u(smem);
    float* bias_s = (float*)(smem + SM_BIAS);
    int*   rows   = (int*)(smem + SM_ROWS);

    int tid = threadIdx.x;
    int wid = tid >> 5, L = tid & 31;

    if (tid < BM) {
        int m = m0 + tid;
        rows[tid] = (m < cnt) ? g_sorted[start + m] : -1;
    }
    if (tid < 16)
        *(float4*)(bias_s + tid * 4) = *(const float4*)(bias + e * POUT + tid * 4);
    __syncthreads();

    // per-thread A-load coords
    const int am = tid >> 4;            // token sub-row (with +8*i stride below)
    const int aq = tid & 15;            // float4 within 64-float chunk
    const int myrow[8] = {0};           // (unused placeholder to keep arrays simple)
    (void)myrow;

    // ldmatrix lane-address components (bytes, pre-swizzle)
    int arow = wid * 16 + (L & 7) + ((L >> 3) & 1) * 8;
    int acol = (L >> 4) * 8;
    int brow = (L & 7) + ((L >> 3) & 1) * 8;
    int bcol = (L >> 4) * 8;

    float acc[8][4];
#pragma unroll
    for (int j = 0; j < 8; j++)
#pragma unroll
        for (int q = 0; q < 4; q++) acc[j][q] = 0.f;

    // ---- A loader: gathered LDG of chunk k0 into fa regs ----
    auto ldg_chunk = [&](int k0, float4 fa[8]) {
#pragma unroll
        for (int i = 0; i < 8; i++) {
            int m = am + i * 16;
            int row = rows[m];
            fa[i] = make_float4(0.f, 0.f, 0.f, 0.f);
            if (row >= 0) fa[i] = *(const float4*)(x + (size_t)row * DIM + k0 + aq * 4);
        }
    };
    // ---- A split+store into buffer ----
    auto sts_chunk = [&](const float4 fa[8], uint32_t bufOff) {
#pragma unroll
        for (int i = 0; i < 8; i++) {
            int m = am + i * 16;
            uint2 hv, lv;
            split4(fa[i], hv, lv);
            uint32_t off = sw128((uint32_t)(m * 128 + aq * 8));
            *(uint2*)(smem + bufOff + off) = hv;
            *(uint2*)(smem + bufOff + 16384 + off) = lv;
        }
    };
    // ---- B copy via cp.async (pre-swizzled tiles) ----
    auto cp_b = [&](int c, uint32_t bufOff) {
        uint32_t bh = sb + bufOff + 32768;
        uint32_t bl = sb + bufOff + 40960;
        const unsigned char* sh = g_Whi[e][c];
        const unsigned char* sl = g_Wlo[e][c];
#pragma unroll
        for (int i = 0; i < 2; i++) {
            uint32_t o = (uint32_t)(tid + i * 256) * 16;
            cpasync16(bh + o, sh + o);
            cpasync16(bl + o, sl + o);
        }
        asm volatile("cp.async.commit_group;" ::: "memory");
    };

    // ---- prologue: stage chunk 0 into buffer 0 ----
    float4 fa[8];
    ldg_chunk(0, fa);
    cp_b(0, SM_BUF);
    sts_chunk(fa, SM_BUF);
    asm volatile("cp.async.wait_group 0;" ::: "memory");
    __syncthreads();

    for (int c = 0; c < NCH; c++) {
        uint32_t buf  = SM_BUF + (uint32_t)(c & 1) * STAGE;
        uint32_t nbuf = SM_BUF + (uint32_t)((c + 1) & 1) * STAGE;
        const uint32_t AHI = sb + buf, ALO = AHI + 16384;
        const uint32_t BHI = AHI + 32768, BLO = AHI + 40960;

        // prefetch next chunk (A regs + B cp.async into other buffer)
        if (c + 1 < NCH) {
            ldg_chunk((c + 1) * CK, fa);
            cp_b(c + 1, nbuf);
        }

        // ---- MMA phase on current buffer ----
#pragma unroll
        for (int s = 0; s < 4; s++) {
            uint32_t aoff = sw128((uint32_t)(arow * 128 + (s * 16 + acol) * 2));
            uint32_t ah[4], al[4];
            ldsm_x4(AHI + aoff, ah);
            ldsm_x4(ALO + aoff, al);
#pragma unroll
            for (int p = 0; p < 4; p++) {
                uint32_t boff = sw128((uint32_t)((s * 16 + brow) * 128 + (p * 16 + bcol) * 2));
                uint32_t bh[4], bl[4];
                ldsm_x4_t(BHI + boff, bh);
                ldsm_x4_t(BLO + boff, bl);
                mma16816(acc[2 * p],     ah, bh[0], bh[1]);
                mma16816(acc[2 * p],     al, bh[0], bh[1]);
                mma16816(acc[2 * p],     ah, bl[0], bl[1]);
                mma16816(acc[2 * p + 1], ah, bh[2], bh[3]);
                mma16816(acc[2 * p + 1], al, bh[2], bh[3]);
                mma16816(acc[2 * p + 1], ah, bl[2], bl[3]);
            }
        }

        // ---- stage next chunk's A into other buffer (overlaps others' MMA) ----
        if (c + 1 < NCH) {
            sts_chunk(fa, nbuf);
            asm volatile("cp.async.wait_group 0;" ::: "memory");
        }
        __syncthreads();
    }

    // ---- epilogue: transpose through smem, coalesced scatter ----
    float* Cs = (float*)(smem + SM_BUF);
    {
        int r = wid * 16 + (L >> 2);
        int cbase = (L & 3) * 2;
#pragma unroll
        for (int j = 0; j < 8; j++) {
            int cc = cbase + j * 8;
            *(float2*)(Cs + r * CS_STRIDE + cc)       = make_float2(acc[j][0], acc[j][1]);
            *(float2*)(Cs + (r + 8) * CS_STRIDE + cc) = make_float2(acc[j][2], acc[j][3]);
        }
    }
    __syncthreads();
    {
        int r = tid >> 1;
        int half = tid & 1;
        int row = rows[r];
        if (row >= 0) {
            float* op = out + (size_t)row * POUT;
#pragma unroll
            for (int q = 0; q < 8; q++) {
                int c4 = half * 8 + q;
                float4 v = *(float4*)(Cs + r * CS_STRIDE + c4 * 4);
                float4 bv = *(float4*)(bias_s + c4 * 4);
                v.x += bv.x; v.y += bv.y; v.z += bv.z; v.w += bv.w;
                *(float4*)(op + c4 * 4) = v;
            }
        }
    }
}

// ---------------- launch ----------------
extern "C" void kernel_launch(void* const* d_in, const int* in_sizes, int n_in,
                              void* d_out, int out_size) {
    const float* x   = (const float*)d_in[0];  // [32,8192,256]
    const float* W   = (const float*)d_in[1];  // [16,256,64]
    const float* b   = (const float*)d_in[2];  // [16,64]
    const int*   idx = (const int*)d_in[3];    // [32,8192]
    float* out = (float*)d_out;                // [32,8192,64]

    cudaFuncSetAttribute(k_gemm_mma, cudaFuncAttributeMaxDynamicSharedMemorySize, SMEM_TOTAL);

    k_init<<<1, 32>>>();
    k_hist<<<NTOK / (256 * 4), 256>>>(idx);
    k_scan<<<1, 32>>>();
    k_scatter<<<NTOK / 256, 256>>>(idx);
    k_wsplit<<<NEXP * NCH, 256>>>(W);

    int max_tiles = NTOK / BM + NEXP;
    k_gemm_mma<<<max_tiles, 256, SMEM_TOTAL>>>(x, b, out);
}